// round 3
// baseline (speedup 1.0000x reference)
#include <cuda_runtime.h>
#include <cstdint>

#define NN 50000
#define NE 800000

// ---------------- device scratch (static; no allocations allowed) ----------------
__device__ int   g_rowstart[NN + 1];
__device__ int   g_cursor[NN];
__device__ int   g_esrc[NE];
__device__ float g_ewt[NE];
__device__ float g_aggx[(size_t)NN * 96];   // gconv(x) for all (f,t): col = f*12+t
__device__ float g_h0[(size_t)NN * 64];
__device__ float g_h1[(size_t)NN * 64];
__device__ float g_rh[(size_t)NN * 64];     // r*h scratch (layer0 then layer1)
__device__ float g_z [(size_t)NN * 64];     // z scratch (layer0 then layer1)
__device__ float g_A72[(size_t)NN * 72];    // GEMM input, layer0 (gate then cand)
__device__ float g_A3[(size_t)NN * 128];    // GEMM input, layer1 gate = [agg(h0), agg(h1)]
__device__ float g_A4[(size_t)NN * 128];    // GEMM input, layer1 cand = [agg(h0), agg(r*h1)]

// ---------------- init ----------------
__global__ void k_init() {
    int i = blockIdx.x * blockDim.x + threadIdx.x;
    size_t tot = (size_t)NN * 64;
    if ((size_t)i < tot) { g_h0[i] = 0.f; g_h1[i] = 0.f; }
    if (i < NN) g_cursor[i] = 0;
}

__global__ void k_count(const int* __restrict__ dst, int E) {
    int i = blockIdx.x * blockDim.x + threadIdx.x;
    if (i < E) atomicAdd(&g_cursor[dst[i]], 1);
}

// single-block exclusive scan of g_cursor -> g_rowstart; also primes g_cursor=rowstart
__global__ void k_scan() {
    __shared__ int sums[1024];
    int tid = threadIdx.x;
    const int CH = (NN + 1023) / 1024;  // 49
    int base = tid * CH;
    int s = 0;
    for (int i = 0; i < CH; i++) {
        int idx = base + i;
        if (idx < NN) s += g_cursor[idx];
    }
    sums[tid] = s;
    __syncthreads();
    for (int off = 1; off < 1024; off <<= 1) {
        int v = 0;
        if (tid >= off) v = sums[tid - off];
        __syncthreads();
        sums[tid] += v;
        __syncthreads();
    }
    int run = (tid == 0) ? 0 : sums[tid - 1];
    for (int i = 0; i < CH; i++) {
        int idx = base + i;
        if (idx < NN) {
            int c = g_cursor[idx];
            g_rowstart[idx] = run;
            g_cursor[idx]   = run;
            run += c;
        }
    }
    if (tid == 0) g_rowstart[NN] = sums[1023];
}

__global__ void k_scatter(const int* __restrict__ src, const int* __restrict__ dst,
                          const float* __restrict__ w, int E) {
    int i = blockIdx.x * blockDim.x + threadIdx.x;
    if (i < E) {
        int d = dst[i];
        int p = atomicAdd(&g_cursor[d], 1);
        g_esrc[p] = src[i];
        g_ewt[p]  = w[i];
    }
}

// ---------------- aggregation kernels: warp per node ----------------
// edges of node n: [rowstart[n], rowstart[n+1]); batched 32 at a time, shfl broadcast.

__global__ void k_aggx(const float* __restrict__ x) {
    int n = (blockIdx.x * blockDim.x + threadIdx.x) >> 5;
    int lane = threadIdx.x & 31;
    if (n >= NN) return;
    int s0 = g_rowstart[n], s1 = g_rowstart[n + 1];
    float a0 = 0.f, a1 = 0.f, a2 = 0.f;
    for (int e = s0; e < s1; e += 32) {
        int idx = e + lane;
        int src = 0; float w = 0.f;
        if (idx < s1) { src = g_esrc[idx]; w = g_ewt[idx]; }
        int cnt = min(32, s1 - e);
        #pragma unroll 4
        for (int k = 0; k < cnt; k++) {
            int   ss = __shfl_sync(0xffffffffu, src, k);
            float ww = __shfl_sync(0xffffffffu, w,   k);
            const float* fp = x + (size_t)ss * 96;
            a0 += ww * fp[lane];
            a1 += ww * fp[lane + 32];
            a2 += ww * fp[lane + 64];
        }
    }
    float* op = g_aggx + (size_t)n * 96;
    op[lane] = a0; op[lane + 32] = a1; op[lane + 64] = a2;
}

// agg of a 64-col feature table (RH ? g_rh : g_h0) into A72 cols [8..71];
// cols [0..7] = aggx slice @ t
template<bool RH>
__global__ void k_agg_s12(int t) {
    const float* feat = RH ? g_rh : g_h0;
    int n = (blockIdx.x * blockDim.x + threadIdx.x) >> 5;
    int lane = threadIdx.x & 31;
    if (n >= NN) return;
    int s0 = g_rowstart[n], s1 = g_rowstart[n + 1];
    float a0 = 0.f, a1 = 0.f;
    for (int e = s0; e < s1; e += 32) {
        int idx = e + lane;
        int src = 0; float w = 0.f;
        if (idx < s1) { src = g_esrc[idx]; w = g_ewt[idx]; }
        int cnt = min(32, s1 - e);
        #pragma unroll 4
        for (int k = 0; k < cnt; k++) {
            int   ss = __shfl_sync(0xffffffffu, src, k);
            float ww = __shfl_sync(0xffffffffu, w,   k);
            const float* fp = feat + (size_t)ss * 64;
            a0 += ww * fp[lane];
            a1 += ww * fp[lane + 32];
        }
    }
    float* op = g_A72 + (size_t)n * 72;
    op[8 + lane]  = a0;
    op[40 + lane] = a1;
    if (lane < 8) op[lane] = g_aggx[(size_t)n * 96 + lane * 12 + t];
}

// agg of h0 and h1 into A3 = [agg(h0)(64), agg(h1)(64)]
__global__ void k_agg_s3() {
    int n = (blockIdx.x * blockDim.x + threadIdx.x) >> 5;
    int lane = threadIdx.x & 31;
    if (n >= NN) return;
    int s0 = g_rowstart[n], s1 = g_rowstart[n + 1];
    float a0 = 0.f, a1 = 0.f, a2 = 0.f, a3 = 0.f;
    for (int e = s0; e < s1; e += 32) {
        int idx = e + lane;
        int src = 0; float w = 0.f;
        if (idx < s1) { src = g_esrc[idx]; w = g_ewt[idx]; }
        int cnt = min(32, s1 - e);
        #pragma unroll 4
        for (int k = 0; k < cnt; k++) {
            int   ss = __shfl_sync(0xffffffffu, src, k);
            float ww = __shfl_sync(0xffffffffu, w,   k);
            const float* f0 = g_h0 + (size_t)ss * 64;
            const float* f1 = g_h1 + (size_t)ss * 64;
            a0 += ww * f0[lane];
            a1 += ww * f0[lane + 32];
            a2 += ww * f1[lane];
            a3 += ww * f1[lane + 32];
        }
    }
    float* op = g_A3 + (size_t)n * 128;
    op[lane] = a0; op[lane + 32] = a1; op[64 + lane] = a2; op[96 + lane] = a3;
}

// agg of rh (=r1*h1) into A4 cols [64..127]; cols [0..63] copied from A3 (agg(h0))
__global__ void k_agg_s4() {
    int n = (blockIdx.x * blockDim.x + threadIdx.x) >> 5;
    int lane = threadIdx.x & 31;
    if (n >= NN) return;
    int s0 = g_rowstart[n], s1 = g_rowstart[n + 1];
    float a0 = 0.f, a1 = 0.f;
    for (int e = s0; e < s1; e += 32) {
        int idx = e + lane;
        int src = 0; float w = 0.f;
        if (idx < s1) { src = g_esrc[idx]; w = g_ewt[idx]; }
        int cnt = min(32, s1 - e);
        #pragma unroll 4
        for (int k = 0; k < cnt; k++) {
            int   ss = __shfl_sync(0xffffffffu, src, k);
            float ww = __shfl_sync(0xffffffffu, w,   k);
            const float* fp = g_rh + (size_t)ss * 64;
            a0 += ww * fp[lane];
            a1 += ww * fp[lane + 32];
        }
    }
    const float* ip = g_A3 + (size_t)n * 128;
    float*       op = g_A4 + (size_t)n * 128;
    op[64 + lane] = a0; op[96 + lane] = a1;
    op[lane]      = ip[lane];
    op[32 + lane] = ip[32 + lane];
}

// ---------------- tiled GEMM with fused gate/candidate epilogue ----------------
// SEL: 0 = layer0 (A=g_A72, K=72, h=g_h0)
//      1 = layer1 gate (A=g_A3, K=128, h=g_h1)
//      2 = layer1 cand (A=g_A4, K=128, h=g_h1)
// GATE: NOUT=128, rz=sigmoid -> g_rh=r*h (j<64), g_z=z (j>=64).
// !GATE: NOUT=64, c=tanh -> h = z*h + (1-z)*c (in place).
__device__ __forceinline__ float fsig(float x)  { return 1.f / (1.f + __expf(-x)); }
__device__ __forceinline__ float ftanh(float x) { return 2.f / (1.f + __expf(-2.f * x)) - 1.f; }

template<int SEL, bool GATE>
__global__ void __launch_bounds__(256) k_gemm(const float* __restrict__ W,
                                              const float* __restrict__ B) {
    constexpr int K    = (SEL == 0) ? 72 : 128;
    constexpr int NOUT = GATE ? 128 : 64;
    const float* __restrict__ A = (SEL == 0) ? g_A72 : (SEL == 1) ? g_A3 : g_A4;
    float* __restrict__ h = (SEL == 0) ? g_h0 : g_h1;

    constexpr int BM = 128, BN = 64, BK = 32;
    __shared__ __align__(16) float As[BM][BK];
    __shared__ __align__(16) float Ws[BK][BN];
    int tid = threadIdx.x;
    int rowBlock = blockIdx.x * BM;
    int colBlock = blockIdx.y * BN;
    int rg = tid >> 4;        // 0..15
    int cg = tid & 15;        // 0..15
    int r0 = rg * 8;
    int c0 = cg * 4;

    unsigned long long acc[8][2];
    #pragma unroll
    for (int i = 0; i < 8; i++) { acc[i][0] = 0ull; acc[i][1] = 0ull; }

    for (int kc = 0; kc < K; kc += BK) {
        #pragma unroll
        for (int l = 0; l < 16; l++) {
            int idx = tid + l * 256;      // 0..4095
            int r = idx >> 5;
            int kk = idx & 31;
            int gr = rowBlock + r;
            int gk = kc + kk;
            float v = 0.f;
            if (gr < NN && gk < K) v = A[(size_t)gr * K + gk];
            As[r][kk] = v;
        }
        #pragma unroll
        for (int l = 0; l < 8; l++) {
            int idx = tid + l * 256;      // 0..2047
            int kk = idx >> 6;
            int j = idx & 63;
            int gk = kc + kk;
            float v = 0.f;
            if (gk < K) v = W[(size_t)gk * NOUT + colBlock + j];
            Ws[kk][j] = v;
        }
        __syncthreads();
        #pragma unroll
        for (int kk = 0; kk < BK; kk++) {
            float4 b = *reinterpret_cast<const float4*>(&Ws[kk][c0]);
            unsigned long long b0, b1;
            asm("mov.b64 %0,{%1,%2};" : "=l"(b0) : "f"(b.x), "f"(b.y));
            asm("mov.b64 %0,{%1,%2};" : "=l"(b1) : "f"(b.z), "f"(b.w));
            #pragma unroll
            for (int i = 0; i < 8; i++) {
                float a = As[r0 + i][kk];
                unsigned long long a2;
                asm("mov.b64 %0,{%1,%1};" : "=l"(a2) : "f"(a));
                asm("fma.rn.f32x2 %0,%1,%2,%0;" : "+l"(acc[i][0]) : "l"(a2), "l"(b0));
                asm("fma.rn.f32x2 %0,%1,%2,%0;" : "+l"(acc[i][1]) : "l"(a2), "l"(b1));
            }
        }
        __syncthreads();
    }

    #pragma unroll
    for (int i = 0; i < 8; i++) {
        int n = rowBlock + r0 + i;
        if (n < NN) {
            float v[4];
            asm("mov.b64 {%0,%1},%2;" : "=f"(v[0]), "=f"(v[1]) : "l"(acc[i][0]));
            asm("mov.b64 {%0,%1},%2;" : "=f"(v[2]), "=f"(v[3]) : "l"(acc[i][1]));
            #pragma unroll
            for (int q = 0; q < 4; q++) {
                int j = colBlock + c0 + q;
                float val = v[q] + B[j];
                if (GATE) {
                    float s = fsig(val);
                    if (j < 64) g_rh[(size_t)n * 64 + j] = s * h[(size_t)n * 64 + j];
                    else        g_z[(size_t)n * 64 + (j - 64)] = s;
                } else {
                    float c  = ftanh(val);
                    float zz = g_z[(size_t)n * 64 + j];
                    float hh = h[(size_t)n * 64 + j];
                    h[(size_t)n * 64 + j] = zz * hh + (1.f - zz) * c;
                }
            }
        }
    }
}

// ---------------- output head: out[n] = h1[n,:] . Wout + bout ----------------
__global__ void k_out(const float* __restrict__ Wout, const float* __restrict__ bout,
                      float* __restrict__ out) {
    int n = (blockIdx.x * blockDim.x + threadIdx.x) >> 5;
    int lane = threadIdx.x & 31;
    if (n >= NN) return;
    const float* hp = g_h1 + (size_t)n * 64;
    float s = hp[lane] * Wout[lane] + hp[lane + 32] * Wout[lane + 32];
    #pragma unroll
    for (int off = 16; off > 0; off >>= 1)
        s += __shfl_down_sync(0xffffffffu, s, off);
    if (lane == 0) out[n] = s + bout[0];
}

// ---------------- host launcher ----------------
extern "C" void kernel_launch(void* const* d_in, const int* in_sizes, int n_in,
                              void* d_out, int out_size) {
    const float* x    = (const float*)d_in[0];
    const int*   ei   = (const int*)  d_in[1];
    const float* ew   = (const float*)d_in[2];
    const float* Wg0  = (const float*)d_in[3];
    const float* bg0  = (const float*)d_in[4];
    const float* Wc0  = (const float*)d_in[5];
    const float* bc0  = (const float*)d_in[6];
    const float* Wg1  = (const float*)d_in[7];
    const float* bg1  = (const float*)d_in[8];
    const float* Wc1  = (const float*)d_in[9];
    const float* bc1  = (const float*)d_in[10];
    const float* Wout = (const float*)d_in[11];
    const float* bout = (const float*)d_in[12];

    int E = in_sizes[1] / 2;
    if (E > NE) E = NE;
    const int* src = ei;
    const int* dst = ei + E;

    // init + CSR build
    {
        size_t tot = (size_t)NN * 64;
        k_init<<<(int)((tot + 255) / 256), 256>>>();
    }
    k_count<<<(E + 255) / 256, 256>>>(dst, E);
    k_scan<<<1, 1024>>>();
    k_scatter<<<(E + 255) / 256, 256>>>(src, dst, ew, E);

    const int AGG_BLOCKS = (NN + 7) / 8;          // 8 warps/block
    k_aggx<<<AGG_BLOCKS, 256>>>(x);

    const int GM = (NN + 127) / 128;              // 391 row tiles

    for (int t = 0; t < 12; t++) {
        // layer 0 gates
        k_agg_s12<false><<<AGG_BLOCKS, 256>>>(t);
        k_gemm<0, true><<<dim3(GM, 2), 256>>>(Wg0, bg0);
        // layer 0 candidate + update (h0 in place)
        k_agg_s12<true><<<AGG_BLOCKS, 256>>>(t);
        k_gemm<0, false><<<dim3(GM, 1), 256>>>(Wc0, bc0);
        // layer 1 gates
        k_agg_s3<<<AGG_BLOCKS, 256>>>();
        k_gemm<1, true><<<dim3(GM, 2), 256>>>(Wg1, bg1);
        // layer 1 candidate + update (h1 in place)
        k_agg_s4<<<AGG_BLOCKS, 256>>>();
        k_gemm<2, false><<<dim3(GM, 1), 256>>>(Wc1, bc1);
    }

    k_out<<<AGG_BLOCKS, 256>>>(Wout, bout, (float*)d_out);
}

// round 4
// speedup vs baseline: 1.0077x; 1.0077x over previous
#include <cuda_runtime.h>
#include <cuda_fp16.h>
#include <cstdint>

#define NN 50000
#define NE 800000

// ---------------- device scratch ----------------
__device__ int      g_rowstart[NN + 1];
__device__ int      g_cursor[NN];
__device__ int      g_esrc[NE];
__device__ float    g_ewt[NE];
__device__ float    g_aggx[(size_t)NN * 96];   // gconv(x) all (f,t): col = f*12+t
__device__ float    g_h0[(size_t)NN * 64];     // fp32 states
__device__ float    g_h1[(size_t)NN * 64];
__device__ float    g_z [(size_t)NN * 64];     // z scratch (fp32)
__device__ unsigned g_h0h[(size_t)NN * 32];    // half2 gather mirrors
__device__ unsigned g_h1h[(size_t)NN * 32];
__device__ unsigned g_rhh[(size_t)NN * 32];    // r*h (half2), layer0 then layer1
__device__ float    g_A72[(size_t)NN * 72];    // layer0 GEMM input
__device__ float    g_A3[(size_t)NN * 128];    // layer1 gate input = [agg(h0)|agg(h1)]
__device__ float    g_A4b[(size_t)NN * 64];    // layer1 cand input cols 64..127 = agg(r*h1)

// ---------------- init ----------------
__global__ void k_init() {
    int i = blockIdx.x * blockDim.x + threadIdx.x;
    size_t tot = (size_t)NN * 64;
    if ((size_t)i < tot) { g_h0[i] = 0.f; g_h1[i] = 0.f; }
    size_t toth = (size_t)NN * 32;
    if ((size_t)i < toth) { g_h0h[i] = 0u; g_h1h[i] = 0u; }
    if (i < NN) g_cursor[i] = 0;
}

__global__ void k_count(const int* __restrict__ dst, int E) {
    int i = blockIdx.x * blockDim.x + threadIdx.x;
    if (i < E) atomicAdd(&g_cursor[dst[i]], 1);
}

__global__ void k_scan() {
    __shared__ int sums[1024];
    int tid = threadIdx.x;
    const int CH = (NN + 1023) / 1024;
    int base = tid * CH;
    int s = 0;
    for (int i = 0; i < CH; i++) {
        int idx = base + i;
        if (idx < NN) s += g_cursor[idx];
    }
    sums[tid] = s;
    __syncthreads();
    for (int off = 1; off < 1024; off <<= 1) {
        int v = 0;
        if (tid >= off) v = sums[tid - off];
        __syncthreads();
        sums[tid] += v;
        __syncthreads();
    }
    int run = (tid == 0) ? 0 : sums[tid - 1];
    for (int i = 0; i < CH; i++) {
        int idx = base + i;
        if (idx < NN) {
            int c = g_cursor[idx];
            g_rowstart[idx] = run;
            g_cursor[idx]   = run;
            run += c;
        }
    }
    if (tid == 0) g_rowstart[NN] = sums[1023];
}

__global__ void k_scatter(const int* __restrict__ src, const int* __restrict__ dst,
                          const float* __restrict__ w, int E) {
    int i = blockIdx.x * blockDim.x + threadIdx.x;
    if (i < E) {
        int d = dst[i];
        int p = atomicAdd(&g_cursor[d], 1);
        g_esrc[p] = src[i];
        g_ewt[p]  = w[i];
    }
}

// ---------------- aggregation: warp per node, shfl-broadcast edges ----------------

__global__ void k_aggx(const float* __restrict__ x) {
    int n = (blockIdx.x * blockDim.x + threadIdx.x) >> 5;
    int lane = threadIdx.x & 31;
    if (n >= NN) return;
    int s0 = g_rowstart[n], s1 = g_rowstart[n + 1];
    float a0 = 0.f, a1 = 0.f, a2 = 0.f;
    for (int e = s0; e < s1; e += 32) {
        int idx = e + lane;
        int src = 0; float w = 0.f;
        if (idx < s1) { src = g_esrc[idx]; w = g_ewt[idx]; }
        int cnt = min(32, s1 - e);
        #pragma unroll 4
        for (int k = 0; k < cnt; k++) {
            int   ss = __shfl_sync(0xffffffffu, src, k);
            float ww = __shfl_sync(0xffffffffu, w,   k);
            const float* fp = x + (size_t)ss * 96;
            a0 += ww * fp[lane];
            a1 += ww * fp[lane + 32];
            a2 += ww * fp[lane + 64];
        }
    }
    float* op = g_aggx + (size_t)n * 96;
    op[lane] = a0; op[lane + 32] = a1; op[lane + 64] = a2;
}

// agg of half2 table (RH ? g_rhh : g_h0h) into A72 cols [8..71]; cols[0..7]=aggx@t
template<bool RH>
__global__ void k_agg_s12(int t) {
    const unsigned* __restrict__ feat = RH ? g_rhh : g_h0h;
    int n = (blockIdx.x * blockDim.x + threadIdx.x) >> 5;
    int lane = threadIdx.x & 31;
    if (n >= NN) return;
    int s0 = g_rowstart[n], s1 = g_rowstart[n + 1];
    float a0 = 0.f, a1 = 0.f;
    for (int e = s0; e < s1; e += 32) {
        int idx = e + lane;
        int src = 0; float w = 0.f;
        if (idx < s1) { src = g_esrc[idx]; w = g_ewt[idx]; }
        int cnt = min(32, s1 - e);
        #pragma unroll 4
        for (int k = 0; k < cnt; k++) {
            int   ss = __shfl_sync(0xffffffffu, src, k);
            float ww = __shfl_sync(0xffffffffu, w,   k);
            unsigned v = feat[(size_t)ss * 32 + lane];
            float2 f = __half22float2(*reinterpret_cast<const __half2*>(&v));
            a0 += ww * f.x;
            a1 += ww * f.y;
        }
    }
    float* op = g_A72 + (size_t)n * 72;
    *reinterpret_cast<float2*>(op + 8 + 2 * lane) = make_float2(a0, a1);
    if (lane < 8) op[lane] = g_aggx[(size_t)n * 96 + lane * 12 + t];
}

// agg of h0h and h1h into A3 = [agg(h0)(64) | agg(h1)(64)]
__global__ void k_agg_s3() {
    int n = (blockIdx.x * blockDim.x + threadIdx.x) >> 5;
    int lane = threadIdx.x & 31;
    if (n >= NN) return;
    int s0 = g_rowstart[n], s1 = g_rowstart[n + 1];
    float a0 = 0.f, a1 = 0.f, a2 = 0.f, a3 = 0.f;
    for (int e = s0; e < s1; e += 32) {
        int idx = e + lane;
        int src = 0; float w = 0.f;
        if (idx < s1) { src = g_esrc[idx]; w = g_ewt[idx]; }
        int cnt = min(32, s1 - e);
        #pragma unroll 4
        for (int k = 0; k < cnt; k++) {
            int   ss = __shfl_sync(0xffffffffu, src, k);
            float ww = __shfl_sync(0xffffffffu, w,   k);
            unsigned v0 = g_h0h[(size_t)ss * 32 + lane];
            unsigned v1 = g_h1h[(size_t)ss * 32 + lane];
            float2 f0 = __half22float2(*reinterpret_cast<const __half2*>(&v0));
            float2 f1 = __half22float2(*reinterpret_cast<const __half2*>(&v1));
            a0 += ww * f0.x; a1 += ww * f0.y;
            a2 += ww * f1.x; a3 += ww * f1.y;
        }
    }
    float* op = g_A3 + (size_t)n * 128;
    *reinterpret_cast<float2*>(op + 2 * lane)      = make_float2(a0, a1);
    *reinterpret_cast<float2*>(op + 64 + 2 * lane) = make_float2(a2, a3);
}

// agg of rhh (=r1*h1) into A4b (64 cols)
__global__ void k_agg_s4() {
    int n = (blockIdx.x * blockDim.x + threadIdx.x) >> 5;
    int lane = threadIdx.x & 31;
    if (n >= NN) return;
    int s0 = g_rowstart[n], s1 = g_rowstart[n + 1];
    float a0 = 0.f, a1 = 0.f;
    for (int e = s0; e < s1; e += 32) {
        int idx = e + lane;
        int src = 0; float w = 0.f;
        if (idx < s1) { src = g_esrc[idx]; w = g_ewt[idx]; }
        int cnt = min(32, s1 - e);
        #pragma unroll 4
        for (int k = 0; k < cnt; k++) {
            int   ss = __shfl_sync(0xffffffffu, src, k);
            float ww = __shfl_sync(0xffffffffu, w,   k);
            unsigned v = g_rhh[(size_t)ss * 32 + lane];
            float2 f = __half22float2(*reinterpret_cast<const __half2*>(&v));
            a0 += ww * f.x;
            a1 += ww * f.y;
        }
    }
    *reinterpret_cast<float2*>(g_A4b + (size_t)n * 64 + 2 * lane) = make_float2(a0, a1);
}

// ---------------- tiled GEMM with fused gate/candidate epilogue ----------------
// SEL: 0 = layer0 (A=g_A72, K=72, h=g_h0/g_h0h)
//      1 = layer1 gate (A=g_A3, K=128, h=g_h1/g_h1h)
//      2 = layer1 cand (A=[A3 cols0..63 | A4b], K=128, h=g_h1/g_h1h)
// GATE: NOUT=128; y=0 -> r: g_rhh = half2(r*h); y=1 -> g_z = z.
// !GATE: NOUT=64; h = z*h + (1-z)*tanh(.) in place (+half mirror).
__device__ __forceinline__ float fsig(float x)  { return 1.f / (1.f + __expf(-x)); }
__device__ __forceinline__ float ftanh(float x) { return 2.f / (1.f + __expf(-2.f * x)) - 1.f; }

template<int SEL, bool GATE>
__global__ void __launch_bounds__(256) k_gemm(const float* __restrict__ W,
                                              const float* __restrict__ B) {
    constexpr int K    = (SEL == 0) ? 72 : 128;
    constexpr int NOUT = GATE ? 128 : 64;
    float*    __restrict__ h  = (SEL == 0) ? g_h0  : g_h1;
    unsigned* __restrict__ hh = (SEL == 0) ? g_h0h : g_h1h;

    constexpr int BM = 128, BN = 64, BK = 32;
    __shared__ __align__(16) float As[BK][BM];   // transposed
    __shared__ __align__(16) float Ws[BK][BN];
    int tid = threadIdx.x;
    int rowBlock = blockIdx.x * BM;
    int colBlock = blockIdx.y * BN;
    int rg = tid >> 4;        // 0..15
    int cg = tid & 15;        // 0..15
    int r0 = rg * 8;
    int c0 = cg * 4;

    unsigned long long acc[4][4];   // [row-pair p][col q]
    #pragma unroll
    for (int p = 0; p < 4; p++)
        #pragma unroll
        for (int q = 0; q < 4; q++) acc[p][q] = 0ull;

    for (int kc = 0; kc < K; kc += BK) {
        #pragma unroll
        for (int l = 0; l < 16; l++) {
            int idx = tid + l * 256;      // 0..4095
            int kk = idx >> 7;            // 0..31
            int r  = idx & 127;
            int gr = rowBlock + r;
            int gk = kc + kk;
            float v = 0.f;
            if (gr < NN && gk < K) {
                if (SEL == 0)      v = g_A72[(size_t)gr * 72 + gk];
                else if (SEL == 1) v = g_A3[(size_t)gr * 128 + gk];
                else v = (gk < 64) ? g_A3[(size_t)gr * 128 + gk]
                                   : g_A4b[(size_t)gr * 64 + (gk - 64)];
            }
            As[kk][r] = v;
        }
        #pragma unroll
        for (int l = 0; l < 8; l++) {
            int idx = tid + l * 256;      // 0..2047
            int kk = idx >> 6;
            int j = idx & 63;
            int gk = kc + kk;
            float v = 0.f;
            if (gk < K) v = W[(size_t)gk * NOUT + colBlock + j];
            Ws[kk][j] = v;
        }
        __syncthreads();
        #pragma unroll
        for (int kk = 0; kk < BK; kk++) {
            float4 b = *reinterpret_cast<const float4*>(&Ws[kk][c0]);
            unsigned long long bd[4];
            asm("mov.b64 %0,{%1,%1};" : "=l"(bd[0]) : "f"(b.x));
            asm("mov.b64 %0,{%1,%1};" : "=l"(bd[1]) : "f"(b.y));
            asm("mov.b64 %0,{%1,%1};" : "=l"(bd[2]) : "f"(b.z));
            asm("mov.b64 %0,{%1,%1};" : "=l"(bd[3]) : "f"(b.w));
            unsigned long long ap[4];
            #pragma unroll
            for (int p = 0; p < 4; p++)
                ap[p] = *reinterpret_cast<const unsigned long long*>(&As[kk][r0 + 2 * p]);
            #pragma unroll
            for (int p = 0; p < 4; p++)
                #pragma unroll
                for (int q = 0; q < 4; q++)
                    asm("fma.rn.f32x2 %0,%1,%2,%0;" : "+l"(acc[p][q]) : "l"(ap[p]), "l"(bd[q]));
        }
        __syncthreads();
    }

    float bias[4];
    #pragma unroll
    for (int q = 0; q < 4; q++) bias[q] = B[colBlock + c0 + q];

    #pragma unroll
    for (int p = 0; p < 4; p++) {
        float vlo[4], vhi[4];
        #pragma unroll
        for (int q = 0; q < 4; q++)
            asm("mov.b64 {%0,%1},%2;" : "=f"(vlo[q]), "=f"(vhi[q]) : "l"(acc[p][q]));
        #pragma unroll
        for (int half = 0; half < 2; half++) {
            int n = rowBlock + r0 + 2 * p + half;
            if (n >= NN) continue;
            float v[4];
            #pragma unroll
            for (int q = 0; q < 4; q++) v[q] = (half ? vhi[q] : vlo[q]) + bias[q];
            if (GATE) {
                if (colBlock == 0) {
                    // r -> rhh = half2(r * h)
                    float4 h4 = *reinterpret_cast<const float4*>(&h[(size_t)n * 64 + c0]);
                    float r0v = fsig(v[0]) * h4.x;
                    float r1v = fsig(v[1]) * h4.y;
                    float r2v = fsig(v[2]) * h4.z;
                    float r3v = fsig(v[3]) * h4.w;
                    __half2 p0 = __floats2half2_rn(r0v, r1v);
                    __half2 p1 = __floats2half2_rn(r2v, r3v);
                    g_rhh[(size_t)n * 32 + cg * 2]     = *reinterpret_cast<unsigned*>(&p0);
                    g_rhh[(size_t)n * 32 + cg * 2 + 1] = *reinterpret_cast<unsigned*>(&p1);
                } else {
                    float4 z4 = make_float4(fsig(v[0]), fsig(v[1]), fsig(v[2]), fsig(v[3]));
                    *reinterpret_cast<float4*>(&g_z[(size_t)n * 64 + c0]) = z4;
                }
            } else {
                float4 z4 = *reinterpret_cast<const float4*>(&g_z[(size_t)n * 64 + c0]);
                float4 h4 = *reinterpret_cast<const float4*>(&h[(size_t)n * 64 + c0]);
                float h0n = z4.x * h4.x + (1.f - z4.x) * ftanh(v[0]);
                float h1n = z4.y * h4.y + (1.f - z4.y) * ftanh(v[1]);
                float h2n = z4.z * h4.z + (1.f - z4.z) * ftanh(v[2]);
                float h3n = z4.w * h4.w + (1.f - z4.w) * ftanh(v[3]);
                *reinterpret_cast<float4*>(&h[(size_t)n * 64 + c0]) =
                    make_float4(h0n, h1n, h2n, h3n);
                __half2 p0 = __floats2half2_rn(h0n, h1n);
                __half2 p1 = __floats2half2_rn(h2n, h3n);
                hh[(size_t)n * 32 + cg * 2]     = *reinterpret_cast<unsigned*>(&p0);
                hh[(size_t)n * 32 + cg * 2 + 1] = *reinterpret_cast<unsigned*>(&p1);
            }
        }
    }
}

// ---------------- output head ----------------
__global__ void k_out(const float* __restrict__ Wout, const float* __restrict__ bout,
                      float* __restrict__ out) {
    int n = (blockIdx.x * blockDim.x + threadIdx.x) >> 5;
    int lane = threadIdx.x & 31;
    if (n >= NN) return;
    const float* hp = g_h1 + (size_t)n * 64;
    float s = hp[lane] * Wout[lane] + hp[lane + 32] * Wout[lane + 32];
    #pragma unroll
    for (int off = 16; off > 0; off >>= 1)
        s += __shfl_down_sync(0xffffffffu, s, off);
    if (lane == 0) out[n] = s + bout[0];
}

// ---------------- host launcher ----------------
extern "C" void kernel_launch(void* const* d_in, const int* in_sizes, int n_in,
                              void* d_out, int out_size) {
    const float* x    = (const float*)d_in[0];
    const int*   ei   = (const int*)  d_in[1];
    const float* ew   = (const float*)d_in[2];
    const float* Wg0  = (const float*)d_in[3];
    const float* bg0  = (const float*)d_in[4];
    const float* Wc0  = (const float*)d_in[5];
    const float* bc0  = (const float*)d_in[6];
    const float* Wg1  = (const float*)d_in[7];
    const float* bg1  = (const float*)d_in[8];
    const float* Wc1  = (const float*)d_in[9];
    const float* bc1  = (const float*)d_in[10];
    const float* Wout = (const float*)d_in[11];
    const float* bout = (const float*)d_in[12];

    int E = in_sizes[1] / 2;
    if (E > NE) E = NE;
    const int* src = ei;
    const int* dst = ei + E;

    {
        size_t tot = (size_t)NN * 64;
        k_init<<<(int)((tot + 255) / 256), 256>>>();
    }
    k_count<<<(E + 255) / 256, 256>>>(dst, E);
    k_scan<<<1, 1024>>>();
    k_scatter<<<(E + 255) / 256, 256>>>(src, dst, ew, E);

    const int AGG_BLOCKS = (NN + 7) / 8;
    k_aggx<<<AGG_BLOCKS, 256>>>(x);

    const int GM = (NN + 127) / 128;

    for (int t = 0; t < 12; t++) {
        // layer 0 gates
        k_agg_s12<false><<<AGG_BLOCKS, 256>>>(t);
        k_gemm<0, true><<<dim3(GM, 2), 256>>>(Wg0, bg0);
        // layer 0 candidate + update
        k_agg_s12<true><<<AGG_BLOCKS, 256>>>(t);
        k_gemm<0, false><<<dim3(GM, 1), 256>>>(Wc0, bc0);
        // layer 1 gates
        k_agg_s3<<<AGG_BLOCKS, 256>>>();
        k_gemm<1, true><<<dim3(GM, 2), 256>>>(Wg1, bg1);
        // layer 1 candidate + update
        k_agg_s4<<<AGG_BLOCKS, 256>>>();
        k_gemm<2, false><<<dim3(GM, 1), 256>>>(Wc1, bc1);
    }

    k_out<<<AGG_BLOCKS, 256>>>(Wout, bout, (float*)d_out);
}